// round 16
// baseline (speedup 1.0000x reference)
#include <cuda_runtime.h>

#define HW 65536            // 256*256
#define IMGW 256
#define NWIN 32
#define SCALE 0.25f

__device__ float g_qkv[2 * 288 * HW];
__device__ float g_att[2 * 96 * HW];

// ---------- tf32 helpers ----------
__device__ __forceinline__ float tf32_round(float x) {
    unsigned u; asm("cvt.rna.tf32.f32 %0, %1;" : "=r"(u) : "f"(x));
    return __uint_as_float(u);
}
__device__ __forceinline__ void mma_tf32(float& d0, float& d1, float& d2, float& d3,
                                         unsigned a0, unsigned a1, unsigned a2, unsigned a3,
                                         unsigned b0, unsigned b1) {
    asm("mma.sync.aligned.m16n8k8.row.col.f32.tf32.tf32.f32 "
        "{%0,%1,%2,%3},{%4,%5,%6,%7},{%8,%9},{%0,%1,%2,%3};"
        : "+f"(d0), "+f"(d1), "+f"(d2), "+f"(d3)
        : "r"(a0), "r"(a1), "r"(a2), "r"(a3), "r"(b0), "r"(b1));
}

// ---------------------------------------------------------------------------
// Pointwise GEMM, 2-pass tf32 (Y ≈ Wh·Xh + Wh·Xl) — R15 v4 (32Mx32N warps).
// ---------------------------------------------------------------------------
template <int OC>
__global__ __launch_bounds__(256, 3) void mma_gemm(
    const float* __restrict__ X, const float* __restrict__ W,
    const float* __restrict__ Bias, float* __restrict__ Y)
{
    __shared__ __align__(16) float XPhi[2][4][2][260];
    __shared__ __align__(16) float XPlo[2][4][2][260];
    __shared__ __align__(16) float WPhi[12][4][2][36];

    const int b   = blockIdx.z;
    const int o0  = blockIdx.y * 32;
    const int p0  = blockIdx.x * 256;
    const int tid = threadIdx.x;
    const int warp = tid >> 5;
    const int lane = tid & 31;
    const int g = lane >> 2;
    const int t = lane & 3;
    const int nq = warp * 32;

    for (int i = tid; i < 32 * 96; i += 256) {
        int o = i & 31;
        int k = i >> 5;
        WPhi[k >> 3][k & 3][(k >> 2) & 1][o] = tf32_round(W[(o0 + o) * 96 + k]);
    }

    float acc0[4][4], acc1[4][4];
#pragma unroll
    for (int nb = 0; nb < 4; nb++)
#pragma unroll
        for (int r = 0; r < 4; r++) { acc0[nb][r] = 0.f; acc1[nb][r] = 0.f; }

    float4 xv[4];
#pragma unroll
    for (int pss = 0; pss < 4; pss++) {
        int j  = tid + pss * 256;
        int k  = j >> 6;
        int n4 = j & 63;
        xv[pss] = *(const float4*)(X + (size_t)(b * 96 + k) * HW + p0 + n4 * 4);
    }

    for (int kc = 0; kc < 96; kc += 16) {
        __syncthreads();
#pragma unroll
        for (int pss = 0; pss < 4; pss++) {
            int j  = tid + pss * 256;
            int k  = j >> 6;
            int n4 = j & 63;
            int s  = k >> 3;
            int tt = k & 3;
            int comp = (k >> 2) & 1;
            float4 v = xv[pss];
            float4 hi4, lo4;
            hi4.x = tf32_round(v.x);  lo4.x = tf32_round(v.x - hi4.x);
            hi4.y = tf32_round(v.y);  lo4.y = tf32_round(v.y - hi4.y);
            hi4.z = tf32_round(v.z);  lo4.z = tf32_round(v.z - hi4.z);
            hi4.w = tf32_round(v.w);  lo4.w = tf32_round(v.w - hi4.w);
            *(float4*)&XPhi[s][tt][comp][n4 * 4] = hi4;
            *(float4*)&XPlo[s][tt][comp][n4 * 4] = lo4;
        }
        __syncthreads();

        if (kc < 80) {
#pragma unroll
            for (int pss = 0; pss < 4; pss++) {
                int j  = tid + pss * 256;
                int k  = j >> 6;
                int n4 = j & 63;
                xv[pss] = *(const float4*)(X + (size_t)(b * 96 + kc + 16 + k) * HW + p0 + n4 * 4);
            }
        }

#pragma unroll
        for (int s = 0; s < 2; s++) {
            const int sg = (kc >> 3) + s;
            unsigned A00 = __float_as_uint(WPhi[sg][t][0][g]);
            unsigned A01 = __float_as_uint(WPhi[sg][t][0][g + 8]);
            unsigned A02 = __float_as_uint(WPhi[sg][t][1][g]);
            unsigned A03 = __float_as_uint(WPhi[sg][t][1][g + 8]);
            unsigned A10 = __float_as_uint(WPhi[sg][t][0][g + 16]);
            unsigned A11 = __float_as_uint(WPhi[sg][t][0][g + 24]);
            unsigned A12 = __float_as_uint(WPhi[sg][t][1][g + 16]);
            unsigned A13 = __float_as_uint(WPhi[sg][t][1][g + 24]);

#pragma unroll
            for (int nb = 0; nb < 4; nb++) {
                int n = nq + nb * 8 + g;
                unsigned Bh0 = __float_as_uint(XPhi[s][t][0][n]);
                unsigned Bh1 = __float_as_uint(XPhi[s][t][1][n]);
                unsigned Bl0 = __float_as_uint(XPlo[s][t][0][n]);
                unsigned Bl1 = __float_as_uint(XPlo[s][t][1][n]);
                mma_tf32(acc0[nb][0], acc0[nb][1], acc0[nb][2], acc0[nb][3],
                         A00, A01, A02, A03, Bh0, Bh1);
                mma_tf32(acc0[nb][0], acc0[nb][1], acc0[nb][2], acc0[nb][3],
                         A00, A01, A02, A03, Bl0, Bl1);
                mma_tf32(acc1[nb][0], acc1[nb][1], acc1[nb][2], acc1[nb][3],
                         A10, A11, A12, A13, Bh0, Bh1);
                mma_tf32(acc1[nb][0], acc1[nb][1], acc1[nb][2], acc1[nb][3],
                         A10, A11, A12, A13, Bl0, Bl1);
            }
        }
    }

    const int r0 = o0 + g;
    const float bias0 = Bias[r0];
    const float bias1 = Bias[r0 + 8];
    const float bias2 = Bias[r0 + 16];
    const float bias3 = Bias[r0 + 24];
    float* y0 = Y + (size_t)(b * OC + r0)      * HW + p0 + nq + t * 2;
    float* y1 = Y + (size_t)(b * OC + r0 + 8)  * HW + p0 + nq + t * 2;
    float* y2 = Y + (size_t)(b * OC + r0 + 16) * HW + p0 + nq + t * 2;
    float* y3 = Y + (size_t)(b * OC + r0 + 24) * HW + p0 + nq + t * 2;
#pragma unroll
    for (int nb = 0; nb < 4; nb++) {
        *(float2*)(y0 + nb * 8) = make_float2(acc0[nb][0] + bias0, acc0[nb][1] + bias0);
        *(float2*)(y1 + nb * 8) = make_float2(acc0[nb][2] + bias1, acc0[nb][3] + bias1);
        *(float2*)(y2 + nb * 8) = make_float2(acc1[nb][0] + bias2, acc1[nb][1] + bias2);
        *(float2*)(y3 + nb * 8) = make_float2(acc1[nb][2] + bias3, acc1[nb][3] + bias3);
    }
}

// ---------------------------------------------------------------------------
// Window attention via tensor cores. Block = 1 window x 1 head, 128 threads,
// warp = one m16 query tile. QK: mma with rel-pos in the C-init. AV: mma with
// P (unnormalized, tf32) from smem and V^T; 1/den applied at epilogue.
// ---------------------------------------------------------------------------
struct AttnSmem {
    float Ksm[144 * 20];    // [key][d]   tf32
    float Vt[16 * 148];     // [d][key]   tf32
    float Qs[64 * 20];      // [q][d]     tf32(q*SCALE)
    float relA[64 * 12];    // q . rel_h row
    float relB[64 * 12];    // q . rel_w row
    float rhs[23 * 16];
    float rws[23 * 16];
    float Psm[64 * 148];    // [q][key]   tf32(exp(logit))
};

__global__ __launch_bounds__(128) void attn_mma_kernel(
    const float* __restrict__ rel_h, const float* __restrict__ rel_w)
{
    extern __shared__ __align__(16) char dyn[];
    AttnSmem* sm = (AttnSmem*)dyn;

    const int head = blockIdx.x % 6;
    const int win  = blockIdx.x / 6;
    const int b    = win >> 10;
    const int wy   = (win >> 5) & 31;
    const int wx   = win & 31;
    const int tid  = threadIdx.x;

    for (int i = tid; i < 23 * 16; i += 128) {
        sm->rhs[i] = rel_h[i];
        sm->rws[i] = rel_w[i];
    }

    // Q (scaled, tf32)
    {
        const float* qb = g_qkv + ((size_t)b * 288 + head * 16) * HW + (wy * 8) * IMGW + wx * 8;
        for (int i = tid; i < 1024; i += 128) {
            int d = i >> 6, q = i & 63;
            int x = q >> 3, y = q & 7;
            sm->Qs[q * 20 + d] = tf32_round(SCALE * qb[(size_t)d * HW + x * IMGW + y]);
        }
    }
    // K and V^T (tf32; zero outside image)
    {
        const int gy0 = wy * 8 - 2, gx0 = wx * 8 - 2;
        const float* kb = g_qkv + ((size_t)b * 288 + 96 + head * 16) * HW;
        for (int i = tid; i < 2304; i += 128) {
            int d = i / 144, key = i - d * 144;
            int ki = key / 12, kj = key - ki * 12;
            int gy = gy0 + ki, gx = gx0 + kj;
            float kv = 0.f, vv = 0.f;
            if ((unsigned)gy < 256u && (unsigned)gx < 256u) {
                size_t off = (size_t)d * HW + gy * IMGW + gx;
                kv = kb[off];
                vv = kb[off + (size_t)96 * HW];
            }
            sm->Ksm[key * 20 + d] = tf32_round(kv);
            sm->Vt[d * 148 + key] = tf32_round(vv);
        }
    }
    __syncthreads();

    // rel dots: thread (q = tid&63, half = tid>>6) computes 6 ki for relA+relB
    {
        int q = tid & 63, half = tid >> 6;
        int x = q >> 3, y = q & 7;
#pragma unroll
        for (int kk = 0; kk < 6; kk++) {
            int ki = half * 6 + kk;
            const float* rh = &sm->rhs[(ki - x + 11) * 16];
            const float* rw = &sm->rws[(ki - y + 11) * 16];
            float a = 0.f, bb = 0.f;
#pragma unroll
            for (int d = 0; d < 16; d++) {
                float qv = sm->Qs[q * 20 + d];
                a  += qv * rh[d];
                bb += qv * rw[d];
            }
            sm->relA[q * 12 + ki] = a;
            sm->relB[q * 12 + ki] = bb;
        }
    }
    __syncthreads();

    const int warp = tid >> 5;
    const int lane = tid & 31;
    const int g = lane >> 2, t = lane & 3;
    const int r0 = warp * 16 + g, r1 = r0 + 8;

    // Q a-fragments (hoisted)
    float qa[2][4];
#pragma unroll
    for (int s = 0; s < 2; s++) {
        qa[s][0] = sm->Qs[r0 * 20 + t + 8 * s];
        qa[s][1] = sm->Qs[r1 * 20 + t + 8 * s];
        qa[s][2] = sm->Qs[r0 * 20 + t + 4 + 8 * s];
        qa[s][3] = sm->Qs[r1 * 20 + t + 4 + 8 * s];
    }

    float dsum0 = 0.f, dsum1 = 0.f;

    // ---- QK phase: logits = rel + Q.K^T, exp, store P ----
#pragma unroll
    for (int nt = 0; nt < 18; nt++) {
        int col0 = nt * 8 + 2 * t;
        int col1 = col0 + 1;
        int ki0 = col0 / 12, kj0 = col0 - ki0 * 12;
        int ki1 = col1 / 12, kj1 = col1 - ki1 * 12;
        float c0 = sm->relA[r0 * 12 + ki0] + sm->relB[r0 * 12 + kj0];
        float c1 = sm->relA[r0 * 12 + ki1] + sm->relB[r0 * 12 + kj1];
        float c2 = sm->relA[r1 * 12 + ki0] + sm->relB[r1 * 12 + kj0];
        float c3 = sm->relA[r1 * 12 + ki1] + sm->relB[r1 * 12 + kj1];
#pragma unroll
        for (int s = 0; s < 2; s++) {
            unsigned b0 = __float_as_uint(sm->Ksm[(nt * 8 + g) * 20 + t + 8 * s]);
            unsigned b1 = __float_as_uint(sm->Ksm[(nt * 8 + g) * 20 + t + 4 + 8 * s]);
            mma_tf32(c0, c1, c2, c3,
                     __float_as_uint(qa[s][0]), __float_as_uint(qa[s][1]),
                     __float_as_uint(qa[s][2]), __float_as_uint(qa[s][3]), b0, b1);
        }
        float p0 = __expf(c0), p1 = __expf(c1);
        float p2 = __expf(c2), p3 = __expf(c3);
        dsum0 += p0 + p1;
        dsum1 += p2 + p3;
        *(float2*)&sm->Psm[r0 * 148 + col0] = make_float2(tf32_round(p0), tf32_round(p1));
        *(float2*)&sm->Psm[r1 * 148 + col0] = make_float2(tf32_round(p2), tf32_round(p3));
    }

    // row sums across the t-quad (lane = g*4 + t)
    dsum0 += __shfl_xor_sync(0xffffffffu, dsum0, 1);
    dsum0 += __shfl_xor_sync(0xffffffffu, dsum0, 2);
    dsum1 += __shfl_xor_sync(0xffffffffu, dsum1, 1);
    dsum1 += __shfl_xor_sync(0xffffffffu, dsum1, 2);
    float inv0 = 1.f / dsum0, inv1 = 1.f / dsum1;

    __syncwarp();   // P rows are warp-private; warp-level visibility suffices

    // ---- AV phase: O = P . V ----
    float o0[4] = {}, o1[4] = {};
#pragma unroll
    for (int ks = 0; ks < 18; ks++) {
        unsigned a0 = __float_as_uint(sm->Psm[r0 * 148 + ks * 8 + t]);
        unsigned a1 = __float_as_uint(sm->Psm[r1 * 148 + ks * 8 + t]);
        unsigned a2 = __float_as_uint(sm->Psm[r0 * 148 + ks * 8 + t + 4]);
        unsigned a3 = __float_as_uint(sm->Psm[r1 * 148 + ks * 8 + t + 4]);
        {
            unsigned b0 = __float_as_uint(sm->Vt[g * 148 + ks * 8 + t]);
            unsigned b1 = __float_as_uint(sm->Vt[g * 148 + ks * 8 + t + 4]);
            mma_tf32(o0[0], o0[1], o0[2], o0[3], a0, a1, a2, a3, b0, b1);
        }
        {
            unsigned b0 = __float_as_uint(sm->Vt[(8 + g) * 148 + ks * 8 + t]);
            unsigned b1 = __float_as_uint(sm->Vt[(8 + g) * 148 + ks * 8 + t + 4]);
            mma_tf32(o1[0], o1[1], o1[2], o1[3], a0, a1, a2, a3, b0, b1);
        }
    }

    // ---- epilogue: scale by 1/den, scatter to g_att ----
    {
        int x0 = r0 >> 3, y0q = r0 & 7;
        int x1 = r1 >> 3, y1q = r1 & 7;
        float* ob = g_att + ((size_t)b * 96 + head * 16) * HW + (wy * 8) * IMGW + wx * 8;
        int d0 = 2 * t, d1 = d0 + 1;
        ob[(size_t)d0 * HW + x0 * IMGW + y0q] = o0[0] * inv0;
        ob[(size_t)d1 * HW + x0 * IMGW + y0q] = o0[1] * inv0;
        ob[(size_t)d0 * HW + x1 * IMGW + y1q] = o0[2] * inv1;
        ob[(size_t)d1 * HW + x1 * IMGW + y1q] = o0[3] * inv1;
        d0 += 8; d1 += 8;
        ob[(size_t)d0 * HW + x0 * IMGW + y0q] = o1[0] * inv0;
        ob[(size_t)d1 * HW + x0 * IMGW + y0q] = o1[1] * inv0;
        ob[(size_t)d0 * HW + x1 * IMGW + y1q] = o1[2] * inv1;
        ob[(size_t)d1 * HW + x1 * IMGW + y1q] = o1[3] * inv1;
    }
}

// ---------------------------------------------------------------------------
extern "C" void kernel_launch(void* const* d_in, const int* in_sizes, int n_in,
                              void* d_out, int out_size)
{
    (void)in_sizes; (void)n_in; (void)out_size;
    const float* x      = (const float*)d_in[0];
    const float* qkv_w  = (const float*)d_in[1];
    const float* qkv_b  = (const float*)d_in[2];
    const float* proj_w = (const float*)d_in[3];
    const float* proj_b = (const float*)d_in[4];
    const float* rel_h  = (const float*)d_in[5];
    const float* rel_w  = (const float*)d_in[6];
    float* out = (float*)d_out;

    float* qkv_ptr = nullptr;
    float* att_ptr = nullptr;
    cudaGetSymbolAddress((void**)&qkv_ptr, g_qkv);
    cudaGetSymbolAddress((void**)&att_ptr, g_att);

    // opt-in to >48KB dynamic smem for the attention kernel (idempotent)
    cudaFuncSetAttribute(attn_mma_kernel,
                         cudaFuncAttributeMaxDynamicSharedMemorySize,
                         (int)sizeof(AttnSmem));

    // 1) QKV pointwise GEMM (tensor cores, 2-pass tf32)
    mma_gemm<288><<<dim3(HW / 256, 288 / 32, 2), 256>>>(x, qkv_w, qkv_b, qkv_ptr);

    // 2) Windowed halo attention (tensor cores) -> (2,96,HW)
    attn_mma_kernel<<<2 * NWIN * NWIN * 6, 128, sizeof(AttnSmem)>>>(rel_h, rel_w);

    // 3) Output projection (tensor cores, 2-pass tf32)
    mma_gemm<96><<<dim3(HW / 256, 96 / 32, 2), 256>>>(att_ptr, proj_w, proj_b, out);
}

// round 17
// speedup vs baseline: 1.4129x; 1.4129x over previous
#include <cuda_runtime.h>

#define HW 65536            // 256*256
#define IMGW 256
#define NWIN 32
#define SCALE 0.25f

typedef unsigned long long ull;

__device__ float g_qkv[2 * 288 * HW];
__device__ float g_att[2 * 96 * HW];

// ---------- f32x2 helpers ----------
__device__ __forceinline__ ull pack2(float a, float b) {
    ull r; asm("mov.b64 %0,{%1,%2};" : "=l"(r) : "f"(a), "f"(b)); return r;
}
__device__ __forceinline__ float2 unpack2(ull v) {
    float2 r; asm("mov.b64 {%0,%1},%2;" : "=f"(r.x), "=f"(r.y) : "l"(v)); return r;
}
__device__ __forceinline__ ull ffma2(ull a, ull b, ull c) {
    ull d; asm("fma.rn.f32x2 %0,%1,%2,%3;" : "=l"(d) : "l"(a), "l"(b), "l"(c)); return d;
}
__device__ __forceinline__ ull fadd2(ull a, ull b) {
    ull d; asm("add.rn.f32x2 %0,%1,%2;" : "=l"(d) : "l"(a), "l"(b)); return d;
}
__device__ __forceinline__ void lds2x64(ull& a, ull& b, unsigned addr) {
    asm("ld.shared.v2.u64 {%0,%1},[%2];" : "=l"(a), "=l"(b) : "r"(addr));
}

// ---------- tf32 helpers ----------
__device__ __forceinline__ float tf32_round(float x) {
    unsigned u; asm("cvt.rna.tf32.f32 %0, %1;" : "=r"(u) : "f"(x));
    return __uint_as_float(u);
}
__device__ __forceinline__ void mma_tf32(float& d0, float& d1, float& d2, float& d3,
                                         unsigned a0, unsigned a1, unsigned a2, unsigned a3,
                                         unsigned b0, unsigned b1) {
    asm("mma.sync.aligned.m16n8k8.row.col.f32.tf32.tf32.f32 "
        "{%0,%1,%2,%3},{%4,%5,%6,%7},{%8,%9},{%0,%1,%2,%3};"
        : "+f"(d0), "+f"(d1), "+f"(d2), "+f"(d3)
        : "r"(a0), "r"(a1), "r"(a2), "r"(a3), "r"(b0), "r"(b1));
}

// ---------------------------------------------------------------------------
// Pointwise GEMM, 1-pass tf32 (Y ≈ Wh·Xh), v5:
//  - 32Mx32N warp tiles (v4), W staged once, X register double-buffer.
//  - X-lo pass dropped: halves mma count, staging stores, and cvt work.
//    Error budget: +2.8e-4 RMS per GEMM; total ~5e-4 < 1e-3.
// ---------------------------------------------------------------------------
template <int OC>
__global__ __launch_bounds__(256, 4) void mma_gemm(
    const float* __restrict__ X, const float* __restrict__ W,
    const float* __restrict__ Bias, float* __restrict__ Y)
{
    __shared__ __align__(16) float XPhi[2][4][2][260];
    __shared__ __align__(16) float WPhi[12][4][2][36];

    const int b   = blockIdx.z;
    const int o0  = blockIdx.y * 32;
    const int p0  = blockIdx.x * 256;
    const int tid = threadIdx.x;
    const int warp = tid >> 5;
    const int lane = tid & 31;
    const int g = lane >> 2;
    const int t = lane & 3;
    const int nq = warp * 32;

    for (int i = tid; i < 32 * 96; i += 256) {
        int o = i & 31;
        int k = i >> 5;
        WPhi[k >> 3][k & 3][(k >> 2) & 1][o] = tf32_round(W[(o0 + o) * 96 + k]);
    }

    float acc0[4][4], acc1[4][4];
#pragma unroll
    for (int nb = 0; nb < 4; nb++)
#pragma unroll
        for (int r = 0; r < 4; r++) { acc0[nb][r] = 0.f; acc1[nb][r] = 0.f; }

    float4 xv[4];
#pragma unroll
    for (int pss = 0; pss < 4; pss++) {
        int j  = tid + pss * 256;
        int k  = j >> 6;
        int n4 = j & 63;
        xv[pss] = *(const float4*)(X + (size_t)(b * 96 + k) * HW + p0 + n4 * 4);
    }

    for (int kc = 0; kc < 96; kc += 16) {
        __syncthreads();
#pragma unroll
        for (int pss = 0; pss < 4; pss++) {
            int j  = tid + pss * 256;
            int k  = j >> 6;
            int n4 = j & 63;
            int s  = k >> 3;
            int tt = k & 3;
            int comp = (k >> 2) & 1;
            float4 v = xv[pss];
            float4 hi4;
            hi4.x = tf32_round(v.x);
            hi4.y = tf32_round(v.y);
            hi4.z = tf32_round(v.z);
            hi4.w = tf32_round(v.w);
            *(float4*)&XPhi[s][tt][comp][n4 * 4] = hi4;
        }
        __syncthreads();

        if (kc < 80) {
#pragma unroll
            for (int pss = 0; pss < 4; pss++) {
                int j  = tid + pss * 256;
                int k  = j >> 6;
                int n4 = j & 63;
                xv[pss] = *(const float4*)(X + (size_t)(b * 96 + kc + 16 + k) * HW + p0 + n4 * 4);
            }
        }

#pragma unroll
        for (int s = 0; s < 2; s++) {
            const int sg = (kc >> 3) + s;
            unsigned A00 = __float_as_uint(WPhi[sg][t][0][g]);
            unsigned A01 = __float_as_uint(WPhi[sg][t][0][g + 8]);
            unsigned A02 = __float_as_uint(WPhi[sg][t][1][g]);
            unsigned A03 = __float_as_uint(WPhi[sg][t][1][g + 8]);
            unsigned A10 = __float_as_uint(WPhi[sg][t][0][g + 16]);
            unsigned A11 = __float_as_uint(WPhi[sg][t][0][g + 24]);
            unsigned A12 = __float_as_uint(WPhi[sg][t][1][g + 16]);
            unsigned A13 = __float_as_uint(WPhi[sg][t][1][g + 24]);

#pragma unroll
            for (int nb = 0; nb < 4; nb++) {
                int n = nq + nb * 8 + g;
                unsigned Bh0 = __float_as_uint(XPhi[s][t][0][n]);
                unsigned Bh1 = __float_as_uint(XPhi[s][t][1][n]);
                mma_tf32(acc0[nb][0], acc0[nb][1], acc0[nb][2], acc0[nb][3],
                         A00, A01, A02, A03, Bh0, Bh1);
                mma_tf32(acc1[nb][0], acc1[nb][1], acc1[nb][2], acc1[nb][3],
                         A10, A11, A12, A13, Bh0, Bh1);
            }
        }
    }

    const int r0 = o0 + g;
    const float bias0 = Bias[r0];
    const float bias1 = Bias[r0 + 8];
    const float bias2 = Bias[r0 + 16];
    const float bias3 = Bias[r0 + 24];
    float* y0 = Y + (size_t)(b * OC + r0)      * HW + p0 + nq + t * 2;
    float* y1 = Y + (size_t)(b * OC + r0 + 8)  * HW + p0 + nq + t * 2;
    float* y2 = Y + (size_t)(b * OC + r0 + 16) * HW + p0 + nq + t * 2;
    float* y3 = Y + (size_t)(b * OC + r0 + 24) * HW + p0 + nq + t * 2;
#pragma unroll
    for (int nb = 0; nb < 4; nb++) {
        *(float2*)(y0 + nb * 8) = make_float2(acc0[nb][0] + bias0, acc0[nb][1] + bias0);
        *(float2*)(y1 + nb * 8) = make_float2(acc0[nb][2] + bias1, acc0[nb][3] + bias1);
        *(float2*)(y2 + nb * 8) = make_float2(acc1[nb][0] + bias2, acc1[nb][1] + bias2);
        *(float2*)(y3 + nb * 8) = make_float2(acc1[nb][2] + bias3, acc1[nb][3] + bias3);
    }
}

// ---------------------------------------------------------------------------
// Window attention — proven v3 (R14, ~339us).
// ---------------------------------------------------------------------------
__global__ __launch_bounds__(128, 4) void attn_kernel(
    const float* __restrict__ rel_h, const float* __restrict__ rel_w)
{
    __shared__ __align__(16) float ksm[2 * 144 * 20];
    __shared__ __align__(16) float vsm[2 * 144 * 20];
    __shared__ __align__(16) float rhs_[23 * 16];
    __shared__ __align__(16) float rws_[23 * 16];

    const int hp  = blockIdx.x % 3;
    const int win = blockIdx.x / 3;
    const int b   = win >> 10;
    const int wy  = (win >> 5) & 31;
    const int wx  = win & 31;
    const int tid = threadIdx.x;
    const int h0  = hp * 2;

    for (int i = tid; i < 23 * 16; i += 128) {
        rhs_[i] = rel_h[i];
        rws_[i] = rel_w[i];
    }

    const int y0 = wy * 8 - 2, x0 = wx * 8 - 2;
    for (int i = tid; i < 2 * 16 * 144; i += 128) {
        int j  = i % 12;
        int tt = i / 12;
        int ii = tt % 12;  tt /= 12;
        int d  = tt & 15;
        int hh = tt >> 4;
        int gy = y0 + ii, gx = x0 + j;
        float kv = 0.f, vv = 0.f;
        if ((unsigned)gy < 256u && (unsigned)gx < 256u) {
            const float* p = g_qkv +
                ((size_t)b * 288 + 96 + (h0 + hh) * 16 + d) * HW + gy * IMGW + gx;
            kv = p[0];
            vv = p[(size_t)96 * HW];
        }
        int si = (hh * 144 + ii * 12 + j) * 20 + d;
        ksm[si] = kv;
        vsm[si] = vv;
    }
    __syncthreads();

    const int hh   = tid >> 6;
    const int head = h0 + hh;
    const int qi   = tid & 63;
    const int x    = qi >> 3, y = qi & 7;
    const int gy   = wy * 8 + x, gx = wx * 8 + y;

    ull qp[8];
    {
        const float* qb = g_qkv + ((size_t)b * 288 + head * 16) * HW + gy * IMGW + gx;
#pragma unroll
        for (int d = 0; d < 8; d++) {
            float a = SCALE * qb[(size_t)(2 * d) * HW];
            float c = SCALE * qb[(size_t)(2 * d + 1) * HW];
            qp[d] = pack2(a, c);
        }
    }

    float Bv[12];
#pragma unroll
    for (int kj = 0; kj < 12; kj++) {
        const ull* rw = (const ull*)&rws_[(kj - y + 11) * 16];
        ull s0 = 0, s1 = 0;
#pragma unroll
        for (int d = 0; d < 8; d += 2) {
            s0 = ffma2(qp[d],     rw[d],     s0);
            s1 = ffma2(qp[d + 1], rw[d + 1], s1);
        }
        float2 f = unpack2(fadd2(s0, s1));
        Bv[kj] = f.x + f.y;
    }

    float sden0 = 0.f, sden1 = 0.f, sden2 = 0.f, sden3 = 0.f;
    ull acc[8] = {};
    const unsigned kaddr = (unsigned)__cvta_generic_to_shared(&ksm[hh * 144 * 20]);
    const unsigned vaddr = (unsigned)__cvta_generic_to_shared(&vsm[hh * 144 * 20]);

    for (int ki = 0; ki < 12; ki++) {
        float aki;
        {
            const ull* rh = (const ull*)&rhs_[(ki - x + 11) * 16];
            ull s0 = 0, s1 = 0;
#pragma unroll
            for (int d = 0; d < 8; d += 2) {
                s0 = ffma2(qp[d],     rh[d],     s0);
                s1 = ffma2(qp[d + 1], rh[d + 1], s1);
            }
            float2 f = unpack2(fadd2(s0, s1));
            aki = f.x + f.y;
        }

        const unsigned kro = kaddr + ki * 12 * 80;
        const unsigned vro = vaddr + ki * 12 * 80;

        float l[12];
#pragma unroll
        for (int kj = 0; kj < 12; kj++) {
            ull k0, k1, k2, k3, k4, k5, k6, k7;
            lds2x64(k0, k1, kro + kj * 80);
            lds2x64(k2, k3, kro + kj * 80 + 16);
            lds2x64(k4, k5, kro + kj * 80 + 32);
            lds2x64(k6, k7, kro + kj * 80 + 48);
            ull la = pack2(aki, Bv[kj]);
            la = ffma2(qp[0], k0, la);
            la = ffma2(qp[1], k1, la);
            la = ffma2(qp[2], k2, la);
            la = ffma2(qp[3], k3, la);
            la = ffma2(qp[4], k4, la);
            la = ffma2(qp[5], k5, la);
            la = ffma2(qp[6], k6, la);
            la = ffma2(qp[7], k7, la);
            float2 lf = unpack2(la);
            l[kj] = lf.x + lf.y;
        }

        float p[12];
#pragma unroll
        for (int kj = 0; kj < 12; kj++)
            p[kj] = __expf(l[kj]);
        sden0 += p[0] + p[4];
        sden1 += p[1] + p[5];
        sden2 += p[2] + p[6];
        sden3 += p[3] + p[7];
        sden0 += p[8];
        sden1 += p[9];
        sden2 += p[10];
        sden3 += p[11];

#pragma unroll
        for (int kj = 0; kj < 12; kj++) {
            ull pd = pack2(p[kj], p[kj]);
            ull v0, v1, v2, v3, v4, v5, v6, v7;
            lds2x64(v0, v1, vro + kj * 80);
            lds2x64(v2, v3, vro + kj * 80 + 16);
            lds2x64(v4, v5, vro + kj * 80 + 32);
            lds2x64(v6, v7, vro + kj * 80 + 48);
            acc[0] = ffma2(pd, v0, acc[0]);
            acc[1] = ffma2(pd, v1, acc[1]);
            acc[2] = ffma2(pd, v2, acc[2]);
            acc[3] = ffma2(pd, v3, acc[3]);
            acc[4] = ffma2(pd, v4, acc[4]);
            acc[5] = ffma2(pd, v5, acc[5]);
            acc[6] = ffma2(pd, v6, acc[6]);
            acc[7] = ffma2(pd, v7, acc[7]);
        }
    }

    float inv = 1.f / ((sden0 + sden1) + (sden2 + sden3));
    float* outp = g_att + ((size_t)b * 96 + head * 16) * HW + gy * IMGW + gx;
#pragma unroll
    for (int j = 0; j < 8; j++) {
        float2 f = unpack2(acc[j]);
        outp[(size_t)(2 * j) * HW]     = f.x * inv;
        outp[(size_t)(2 * j + 1) * HW] = f.y * inv;
    }
}

// ---------------------------------------------------------------------------
extern "C" void kernel_launch(void* const* d_in, const int* in_sizes, int n_in,
                              void* d_out, int out_size)
{
    (void)in_sizes; (void)n_in; (void)out_size;
    const float* x      = (const float*)d_in[0];
    const float* qkv_w  = (const float*)d_in[1];
    const float* qkv_b  = (const float*)d_in[2];
    const float* proj_w = (const float*)d_in[3];
    const float* proj_b = (const float*)d_in[4];
    const float* rel_h  = (const float*)d_in[5];
    const float* rel_w  = (const float*)d_in[6];
    float* out = (float*)d_out;

    float* qkv_ptr = nullptr;
    float* att_ptr = nullptr;
    cudaGetSymbolAddress((void**)&qkv_ptr, g_qkv);
    cudaGetSymbolAddress((void**)&att_ptr, g_att);

    // 1) QKV pointwise GEMM (tensor cores, 1-pass tf32, pipelined)
    mma_gemm<288><<<dim3(HW / 256, 288 / 32, 2), 256>>>(x, qkv_w, qkv_b, qkv_ptr);

    // 2) Windowed halo attention (FFMA2 v3)
    attn_kernel<<<2 * NWIN * NWIN * 3, 128>>>(rel_h, rel_w);

    // 3) Output projection (tensor cores, 1-pass tf32, pipelined)
    mma_gemm<96><<<dim3(HW / 256, 96 / 32, 2), 256>>>(att_ptr, proj_w, proj_b, out);
}